// round 11
// baseline (speedup 1.0000x reference)
#include <cuda_runtime.h>
#include <cuda_fp16.h>
#include <cstdint>

#define NN 50000
#define HN 25000
#define EE 800000
#define DD 64
#define NND (NN * DD)
#define NH (NND / 2)
#define CSRMAX (EE + 3 * NN + 64)

// ---------------- scratch (device globals; no allocation allowed) ----------
__device__ float g_deg[NN];          // zero-init (BSS); re-zeroed by k_ew1
__device__ int   g_cnt[NN];          // zero-init (BSS); re-zeroed by k_ew1
__device__ int   g_rowptr[NN + 1];
__device__ int   g_cursor[NN];
__device__ int2  g_csrE[CSRMAX];     // (src*32, nrm as int), rows padded to 4

// unified fp16 hi/lo tables, word = fp16 pair (2 dims). [row*32+lane]
__device__ uint2 g_XHt[NN * 32],  g_XHlo[NN * 32];   // X,H      (fillsetup)
__device__ uint2 g_T1t[NN * 32],  g_T1lo[NN * 32];   // TX1,TH1  (spmm1)
__device__ uint2 g_T2t[NN * 32],  g_T2lo[NN * 32];   // TX2,TH2  (spmm2)
__device__ uint32_t g_HRt[NN * 32],   g_HRlo[NN * 32];    // ew1
__device__ uint32_t g_THR1t[NN * 32], g_THR1lo[NN * 32];  // spmm1_HR
__device__ uint32_t g_THR2t[NN * 32], g_THR2lo[NN * 32];  // spmm2_HR

__device__ float g_GA[3u * NND];        // Zx, Rx, Hx
__device__ float g_GB[2u * NND];        // Zh, Rh
__device__ float g_Z [NND];

// pre-split weights, transposed to [mat][dout][kin], fp16 hi/lo
__device__ unsigned short g_Wh[18 * 4096];
__device__ unsigned short g_Wl[18 * 4096];

// ---------------- helpers ---------------------------------------------------

__device__ __forceinline__ void fsplit(float x, unsigned short& h, unsigned short& l) {
    __half hh = __float2half_rn(x);
    float r = x - __half2float(hh);
    __half ll = __float2half_rn(r);
    h = *(unsigned short*)&hh;
    l = *(unsigned short*)&ll;
}

__device__ __forceinline__ void fsplitpack(float2 v, uint32_t& hi, uint32_t& lo) {
    unsigned short h0, l0, h1, l1;
    fsplit(v.x, h0, l0); fsplit(v.y, h1, l1);
    hi = (uint32_t)h0 | ((uint32_t)h1 << 16);
    lo = (uint32_t)l0 | ((uint32_t)l1 << 16);
}

__device__ __forceinline__ float2 rec2(uint32_t h, uint32_t l) {
    float2 a = __half22float2(*(__half2*)&h);
    float2 b = __half22float2(*(__half2*)&l);
    return make_float2(a.x + b.x, a.y + b.y);
}

__device__ __forceinline__ int detect_idx64(const unsigned int* ei) {
    unsigned v = ei[2 * (threadIdx.x & 31) + 1];
    unsigned ball = __ballot_sync(0xffffffffu, v == 0u);
    return ball == 0xffffffffu;
}

// ---------------- launch 0: degree + count (2 edges/thread) ----------------

__global__ void k_edge_deg(const void* __restrict__ ei, const float* __restrict__ ew) {
    int idx64 = detect_idx64((const unsigned int*)ei);
    int e2 = blockIdx.x * blockDim.x + threadIdx.x;
    if (e2 >= EE / 2) return;
    int s0, s1, d0, d1;
    if (idx64) {
        const longlong2* ps = (const longlong2*)ei;
        longlong2 sv = ps[e2];
        longlong2 dv = ps[EE / 2 + e2];
        s0 = (int)sv.x; s1 = (int)sv.y;
        d0 = (int)dv.x; d1 = (int)dv.y;
    } else {
        const int2* ps = (const int2*)ei;
        int2 sv = ps[e2];
        int2 dv = ps[EE / 2 + e2];
        s0 = sv.x; s1 = sv.y;
        d0 = dv.x; d1 = dv.y;
    }
    float2 w = ((const float2*)ew)[e2];
    atomicAdd(&g_deg[s0], w.x);
    atomicAdd(&g_deg[s1], w.y);
    atomicAdd(&g_cnt[d0], 1);
    atomicAdd(&g_cnt[d1], 1);
}

// ---------------- launch 1: exclusive scan over PADDED counts ---------------

__global__ void k_scan() {
    const int T = 1024;
    int t = threadIdx.x;
    const int CH = (NN + T - 1) / T;
    int beg = t * CH;
    int end = beg + CH; if (end > NN) end = NN; if (beg > NN) beg = NN;
    int s = 0;
    for (int i = beg; i < end; i++) s += (g_cnt[i] + 3) & ~3;
    __shared__ int sm[T];
    sm[t] = s; __syncthreads();
    for (int off = 1; off < T; off <<= 1) {
        int v = (t >= off) ? sm[t - off] : 0;
        __syncthreads();
        sm[t] += v;
        __syncthreads();
    }
    int run = sm[t] - s;
    for (int i = beg; i < end; i++) {
        g_rowptr[i] = run; g_cursor[i] = run;
        run += (g_cnt[i] + 3) & ~3;
    }
    if (t == T - 1) g_rowptr[NN] = run;
}

// ---------------- launch 2: CSR fill + pad + tables + weight split ----------

__global__ void k_fillsetup(const void* __restrict__ ei, const float* __restrict__ ew,
                            const float* __restrict__ X, const float* __restrict__ Hm,
                            const float* __restrict__ W) {
    int i = blockIdx.x * blockDim.x + threadIdx.x;
    if (i < EE) {
        int idx64 = detect_idx64((const unsigned int*)ei);
        int s, d;
        if (idx64) {
            const long long* p = (const long long*)ei;
            s = (int)p[i]; d = (int)p[EE + i];
        } else {
            const int* p = (const int*)ei;
            s = p[i]; d = p[EE + i];
        }
        float ds = g_deg[s], dd = g_deg[d];
        float is = (ds > 0.f) ? rsqrtf(ds) : 0.f;
        float id = (dd > 0.f) ? rsqrtf(dd) : 0.f;
        float nrm = ew[i] * is * id;
        int pos = atomicAdd(&g_cursor[d], 1);
        g_csrE[pos] = make_int2(s * 32, __float_as_int(nrm));
    }
    if (i < NN) {
        int p = g_rowptr[i] + g_cnt[i];
        int pe = g_rowptr[i + 1];
        for (; p < pe; p++) g_csrE[p] = make_int2(0, 0);
    }
    if (i < NH) {
        float2 x = ((const float2*)X)[i];
        float2 h = ((const float2*)Hm)[i];
        uint32_t hx, lx, hh, lh;
        fsplitpack(x, hx, lx);
        fsplitpack(h, hh, lh);
        g_XHt[i]  = make_uint2(hx, hh);
        g_XHlo[i] = make_uint2(lx, lh);
    }
    if (i < 18 * 4096) {
        int mat = i >> 12, kin = (i >> 6) & 63, dout = i & 63;
        unsigned short h, l;
        fsplit(W[i], h, l);
        int o = (mat << 12) | (dout << 6) | kin;
        g_Wh[o] = h;
        g_Wl[o] = l;
    }
}

// ---------------- SpMM gathers: 2 rows per warp (dual chains) ---------------

#define ACC2T(t, w, x0, x1, h0, h1) { float2 _v; \
    _v = __half22float2(*(__half2*)&(t).x); x0 += (w) * _v.x; x1 += (w) * _v.y; \
    _v = __half22float2(*(__half2*)&(t).y); h0 += (w) * _v.x; h1 += (w) * _v.y; }

__device__ __forceinline__ void gather2x2(const uint2* __restrict__ tab,
    int rowA, int rowB, int lane,
    float& AX0, float& AX1, float& AH0, float& AH1,
    float& BX0, float& BX1, float& BH0, float& BH1)
{
    int bA = g_rowptr[rowA];
    int nA = (g_rowptr[rowA + 1] - bA) >> 1;     // 2-edge groups
    int bB = g_rowptr[rowB];
    int nB = (g_rowptr[rowB + 1] - bB) >> 1;
    const uint4* pA = (const uint4*)(g_csrE + bA);
    const uint4* pB = (const uint4*)(g_csrE + bB);
    AX0 = AX1 = AH0 = AH1 = 0.f;
    BX0 = BX1 = BH0 = BH1 = 0.f;
    int nmin = nA < nB ? nA : nB;
    for (int i = 0; i < nmin; i++) {
        uint4 qa = pA[i], qb = pB[i];
        uint2 ta0 = tab[qa.x + lane];
        uint2 ta1 = tab[qa.z + lane];
        uint2 tb0 = tab[qb.x + lane];
        uint2 tb1 = tab[qb.z + lane];
        float wa0 = __int_as_float(qa.y), wa1 = __int_as_float(qa.w);
        float wb0 = __int_as_float(qb.y), wb1 = __int_as_float(qb.w);
        ACC2T(ta0, wa0, AX0, AX1, AH0, AH1);
        ACC2T(ta1, wa1, AX0, AX1, AH0, AH1);
        ACC2T(tb0, wb0, BX0, BX1, BH0, BH1);
        ACC2T(tb1, wb1, BX0, BX1, BH0, BH1);
    }
    for (int i = nmin; i < nA; i++) {
        uint4 qa = pA[i];
        uint2 ta0 = tab[qa.x + lane];
        uint2 ta1 = tab[qa.z + lane];
        float wa0 = __int_as_float(qa.y), wa1 = __int_as_float(qa.w);
        ACC2T(ta0, wa0, AX0, AX1, AH0, AH1);
        ACC2T(ta1, wa1, AX0, AX1, AH0, AH1);
    }
    for (int i = nmin; i < nB; i++) {
        uint4 qb = pB[i];
        uint2 tb0 = tab[qb.x + lane];
        uint2 tb1 = tab[qb.z + lane];
        float wb0 = __int_as_float(qb.y), wb1 = __int_as_float(qb.w);
        ACC2T(tb0, wb0, BX0, BX1, BH0, BH1);
        ACC2T(tb1, wb1, BX0, BX1, BH0, BH1);
    }
}

#define ACC1T(t, w, a0, a1) { float2 _v = __half22float2(*(__half2*)&(t)); \
    a0 += (w) * _v.x; a1 += (w) * _v.y; }

__device__ __forceinline__ void gather1x2(const uint32_t* __restrict__ tab,
    int rowA, int rowB, int lane,
    float& A0, float& A1, float& B0, float& B1)
{
    int bA = g_rowptr[rowA];
    int nA = (g_rowptr[rowA + 1] - bA) >> 1;
    int bB = g_rowptr[rowB];
    int nB = (g_rowptr[rowB + 1] - bB) >> 1;
    const uint4* pA = (const uint4*)(g_csrE + bA);
    const uint4* pB = (const uint4*)(g_csrE + bB);
    A0 = A1 = B0 = B1 = 0.f;
    int nmin = nA < nB ? nA : nB;
    for (int i = 0; i < nmin; i++) {
        uint4 qa = pA[i], qb = pB[i];
        uint32_t ta0 = tab[qa.x + lane];
        uint32_t ta1 = tab[qa.z + lane];
        uint32_t tb0 = tab[qb.x + lane];
        uint32_t tb1 = tab[qb.z + lane];
        float wa0 = __int_as_float(qa.y), wa1 = __int_as_float(qa.w);
        float wb0 = __int_as_float(qb.y), wb1 = __int_as_float(qb.w);
        ACC1T(ta0, wa0, A0, A1);
        ACC1T(ta1, wa1, A0, A1);
        ACC1T(tb0, wb0, B0, B1);
        ACC1T(tb1, wb1, B0, B1);
    }
    for (int i = nmin; i < nA; i++) {
        uint4 qa = pA[i];
        uint32_t ta0 = tab[qa.x + lane];
        uint32_t ta1 = tab[qa.z + lane];
        float wa0 = __int_as_float(qa.y), wa1 = __int_as_float(qa.w);
        ACC1T(ta0, wa0, A0, A1);
        ACC1T(ta1, wa1, A0, A1);
    }
    for (int i = nmin; i < nB; i++) {
        uint4 qb = pB[i];
        uint32_t tb0 = tab[qb.x + lane];
        uint32_t tb1 = tab[qb.z + lane];
        float wb0 = __int_as_float(qb.y), wb1 = __int_as_float(qb.w);
        ACC1T(tb0, wb0, B0, B1);
        ACC1T(tb1, wb1, B0, B1);
    }
}

// per-row epilogue bodies -----------------------------------------------------

__device__ __forceinline__ void t1_body(int row, int lane, float A, float Bc,
    float rX0, float rX1, float rH0, float rH1)
{
    int b32 = row * 32 + lane;
    uint2 th = g_XHt[b32], tl = g_XHlo[b32];
    float2 vx = rec2(th.x, tl.x);
    float2 vh = rec2(th.y, tl.y);
    float2 oX = make_float2(A * vx.x + Bc * rX0, A * vx.y + Bc * rX1);
    float2 oH = make_float2(A * vh.x + Bc * rH0, A * vh.y + Bc * rH1);
    uint32_t hx, lx, hh, lh;
    fsplitpack(oX, hx, lx);
    fsplitpack(oH, hh, lh);
    g_T1t[b32]  = make_uint2(hx, hh);
    g_T1lo[b32] = make_uint2(lx, lh);
}

__device__ __forceinline__ void t2_body(int row, int lane, float A, float Bc,
    float rX0, float rX1, float rH0, float rH1)
{
    int b32 = row * 32 + lane;
    uint2 sh = g_T1t[b32], sl = g_T1lo[b32];
    uint2 ah = g_XHt[b32], al = g_XHlo[b32];
    float2 vx = rec2(sh.x, sl.x), vh = rec2(sh.y, sl.y);
    float2 xx = rec2(ah.x, al.x), xh = rec2(ah.y, al.y);
    float2 oX = make_float2(A * vx.x + Bc * rX0 - xx.x, A * vx.y + Bc * rX1 - xx.y);
    float2 oH = make_float2(A * vh.x + Bc * rH0 - xh.x, A * vh.y + Bc * rH1 - xh.y);
    uint32_t hx, lx, hh, lh;
    fsplitpack(oX, hx, lx);
    fsplitpack(oH, hh, lh);
    g_T2t[b32]  = make_uint2(hx, hh);
    g_T2lo[b32] = make_uint2(lx, lh);
}

// launch 3 (profiled slot): T1 for X and H — 2 rows per warp
__global__ void __launch_bounds__(256) k_spmm1_XH(const float* __restrict__ lam) {
    int warp = threadIdx.x >> 5, lane = threadIdx.x & 31;
    int idx = blockIdx.x * 8 + warp;
    if (idx >= HN) return;
    float c = 2.f / __ldg(lam);
    float A = c - 1.f, Bc = -c;
    float AX0, AX1, AH0, AH1, BX0, BX1, BH0, BH1;
    gather2x2(g_XHt, idx, idx + HN, lane, AX0, AX1, AH0, AH1, BX0, BX1, BH0, BH1);
    t1_body(idx,      lane, A, Bc, AX0, AX1, AH0, AH1);
    t1_body(idx + HN, lane, A, Bc, BX0, BX1, BH0, BH1);
}

// launch 4: T2 for X and H — 2 rows per warp
__global__ void __launch_bounds__(256) k_spmm2_XH(const float* __restrict__ lam) {
    int warp = threadIdx.x >> 5, lane = threadIdx.x & 31;
    int idx = blockIdx.x * 8 + warp;
    if (idx >= HN) return;
    float c = 2.f / __ldg(lam);
    float A = 2.f * (c - 1.f), Bc = -2.f * c;
    float AX0, AX1, AH0, AH1, BX0, BX1, BH0, BH1;
    gather2x2(g_T1t, idx, idx + HN, lane, AX0, AX1, AH0, AH1, BX0, BX1, BH0, BH1);
    t2_body(idx,      lane, A, Bc, AX0, AX1, AH0, AH1);
    t2_body(idx + HN, lane, A, Bc, BX0, BX1, BH0, BH1);
}

__global__ void __launch_bounds__(256) k_spmm1_HR(const float* __restrict__ lam) {
    int warp = threadIdx.x >> 5, lane = threadIdx.x & 31;
    int idx = blockIdx.x * 8 + warp;
    if (idx >= HN) return;
    float c = 2.f / __ldg(lam);
    float A = c - 1.f, Bc = -c;
    float a0, a1, b0, b1;
    gather1x2(g_HRt, idx, idx + HN, lane, a0, a1, b0, b1);
    #pragma unroll
    for (int r = 0; r < 2; r++) {
        int row = idx + r * HN;
        float r0 = r ? b0 : a0, r1 = r ? b1 : a1;
        int b32 = row * 32 + lane;
        float2 v = rec2(g_HRt[b32], g_HRlo[b32]);
        float2 o = make_float2(A * v.x + Bc * r0, A * v.y + Bc * r1);
        uint32_t h, l;
        fsplitpack(o, h, l);
        g_THR1t[b32]  = h;
        g_THR1lo[b32] = l;
    }
}

__global__ void __launch_bounds__(256) k_spmm2_HR(const float* __restrict__ lam) {
    int warp = threadIdx.x >> 5, lane = threadIdx.x & 31;
    int idx = blockIdx.x * 8 + warp;
    if (idx >= HN) return;
    float c = 2.f / __ldg(lam);
    float A = 2.f * (c - 1.f), Bc = -2.f * c;
    float a0, a1, b0, b1;
    gather1x2(g_THR1t, idx, idx + HN, lane, a0, a1, b0, b1);
    #pragma unroll
    for (int r = 0; r < 2; r++) {
        int row = idx + r * HN;
        float r0 = r ? b0 : a0, r1 = r ? b1 : a1;
        int b32 = row * 32 + lane;
        float2 v = rec2(g_THR1t[b32], g_THR1lo[b32]);
        float2 h = rec2(g_HRt[b32], g_HRlo[b32]);
        float2 o = make_float2(A * v.x + Bc * r0 - h.x, A * v.y + Bc * r1 - h.y);
        uint32_t hh, ll;
        fsplitpack(o, hh, ll);
        g_THR2t[b32]  = hh;
        g_THR2lo[b32] = ll;
    }
}

// ---------------- mma.sync fp16 GEMM (M=64 tile, 2 CTAs/SM) ----------------

__device__ __forceinline__ void mma16816(float* c, uint32_t a0, uint32_t a1,
                                         uint32_t a2, uint32_t a3,
                                         uint32_t b0, uint32_t b1) {
    asm volatile(
        "mma.sync.aligned.m16n8k16.row.col.f32.f16.f16.f32 "
        "{%0,%1,%2,%3}, {%4,%5,%6,%7}, {%8,%9}, {%0,%1,%2,%3};"
        : "+f"(c[0]), "+f"(c[1]), "+f"(c[2]), "+f"(c[3])
        : "r"(a0), "r"(a1), "r"(a2), "r"(a3), "r"(b0), "r"(b1));
}

#define ASTR 200
#define EL_AH 0
#define EL_AL 12800
#define EL_BH 25600
#define EL_BL 38400
#define DSM_BYTES (51200 * 2)

__global__ void __launch_bounds__(256) k_gemm_mma(
    const float* __restrict__ Hm, const float* __restrict__ Bb,
    float* __restrict__ OUT, int whichsel)
{
    extern __shared__ unsigned short sm_el[];
    unsigned short* Ah = sm_el + EL_AH;
    unsigned short* Al = sm_el + EL_AL;
    unsigned short* Bh = sm_el + EL_BH;
    unsigned short* Bl = sm_el + EL_BL;

    int tid = threadIdx.x;
    int wid = tid >> 5, lane = tid & 31;
    int rowbase = blockIdx.x * 64;
    int which = (whichsel == 2) ? 2 : (int)blockIdx.y;

    const uint32_t *hsrc[3], *lsrc[3];
    int st, off;
    float* Cbase; int gates, wstart, wstep;
    if (which == 0) {
        hsrc[0] = (const uint32_t*)g_XHt; lsrc[0] = (const uint32_t*)g_XHlo;
        hsrc[1] = (const uint32_t*)g_T1t; lsrc[1] = (const uint32_t*)g_T1lo;
        hsrc[2] = (const uint32_t*)g_T2t; lsrc[2] = (const uint32_t*)g_T2lo;
        st = 2; off = 0; Cbase = g_GA; gates = 3; wstart = 0; wstep = 2;
    } else if (which == 1) {
        hsrc[0] = (const uint32_t*)g_XHt; lsrc[0] = (const uint32_t*)g_XHlo;
        hsrc[1] = (const uint32_t*)g_T1t; lsrc[1] = (const uint32_t*)g_T1lo;
        hsrc[2] = (const uint32_t*)g_T2t; lsrc[2] = (const uint32_t*)g_T2lo;
        st = 2; off = 1; Cbase = g_GB; gates = 2; wstart = 1; wstep = 2;
    } else {
        hsrc[0] = g_HRt;   lsrc[0] = g_HRlo;
        hsrc[1] = g_THR1t; lsrc[1] = g_THR1lo;
        hsrc[2] = g_THR2t; lsrc[2] = g_THR2lo;
        st = 1; off = 0; Cbase = 0; gates = 1; wstart = 5; wstep = 0;
    }

    uint32_t* Ahw = (uint32_t*)Ah;
    uint32_t* Alw = (uint32_t*)Al;
    #pragma unroll
    for (int c = 0; c < 3; c++) {
        const uint32_t* sh = hsrc[c];
        const uint32_t* sl = lsrc[c];
        #pragma unroll
        for (int i = 0; i < 8; i++) {
            int lin = tid + i * 256;
            int m = lin >> 5;
            int k = lin & 31;
            int grow = rowbase + m;
            uint32_t vh = 0, vl = 0;
            if (grow < NN) {
                int idx = (grow * 32 + k) * st + off;
                vh = sh[idx];
                vl = sl[idx];
            }
            int wo = m * 100 + c * 32 + k;
            Ahw[wo] = vh;
            Alw[wo] = vl;
        }
    }
    __syncthreads();

    int gq = lane >> 2, tg = lane & 3;
    int rw = wid & 3, nh = wid >> 2;
    int mrow = rw * 16;
    const uint32_t* pAh = (const uint32_t*)(Ah + (mrow + gq) * ASTR + tg * 2);
    const uint32_t* pAl = (const uint32_t*)(Al + (mrow + gq) * ASTR + tg * 2);
    const uint32_t* pBh0 = (const uint32_t*)(Bh + gq * ASTR + tg * 2) + nh * 3200;
    const uint32_t* pBl0 = (const uint32_t*)(Bl + gq * ASTR + tg * 2) + nh * 3200;

    for (int g = 0; g < gates; g++) {
        int wsel = wstart + g * wstep;
        #pragma unroll
        for (int c = 0; c < 3; c++) {
            int mat = wsel * 3 + c;
            const uint4* srcH = (const uint4*)(g_Wh + (mat << 12));
            const uint4* srcL = (const uint4*)(g_Wl + (mat << 12));
            #pragma unroll
            for (int i = 0; i < 2; i++) {
                int lin = tid + i * 256;
                int d  = lin >> 3;
                int k8 = (lin & 7) * 8;
                int eo = d * ASTR + c * 64 + k8;
                *(uint4*)(Bh + eo) = srcH[lin];
                *(uint4*)(Bl + eo) = srcL[lin];
            }
        }
        __syncthreads();

        float acc[16];
        #pragma unroll
        for (int i = 0; i < 16; i++) acc[i] = 0.f;

        #pragma unroll 2
        for (int ks = 0; ks < 12; ks++) {
            int kw = ks * 8;
            uint32_t ah0 = pAh[kw], ah1 = pAh[kw + 800];
            uint32_t ah2 = pAh[kw + 4], ah3 = pAh[kw + 804];
            uint32_t al0 = pAl[kw], al1 = pAl[kw + 800];
            uint32_t al2 = pAl[kw + 4], al3 = pAl[kw + 804];
            #pragma unroll
            for (int nt = 0; nt < 4; nt++) {
                int bo = nt * 800 + kw;
                uint32_t bh0 = pBh0[bo], bh1 = pBh0[bo + 4];
                uint32_t bl0 = pBl0[bo], bl1 = pBl0[bo + 4];
                float* a = acc + nt * 4;
                mma16816(a, ah0, ah1, ah2, ah3, bh0, bh1);
                mma16816(a, ah0, ah1, ah2, ah3, bl0, bl1);
                mma16816(a, al0, al1, al2, al3, bh0, bh1);
            }
        }

        int r0 = rowbase + mrow + gq;
        int r1 = r0 + 8;
        if (whichsel != 2) {
            float* C = Cbase + (size_t)g * NND;
            #pragma unroll
            for (int nt = 0; nt < 4; nt++) {
                int col = (nh * 4 + nt) * 8 + tg * 2;
                if (r0 < NN) *(float2*)(C + (size_t)r0 * DD + col) = make_float2(acc[nt*4+0], acc[nt*4+1]);
                if (r1 < NN) *(float2*)(C + (size_t)r1 * DD + col) = make_float2(acc[nt*4+2], acc[nt*4+3]);
            }
        } else {
            #pragma unroll
            for (int nt = 0; nt < 4; nt++) {
                int col = (nh * 4 + nt) * 8 + tg * 2;
                float bs0 = __ldg(Bb + 256 + col)     + __ldg(Bb + 320 + col);
                float bs1 = __ldg(Bb + 256 + col + 1) + __ldg(Bb + 320 + col + 1);
                if (r0 < NN) {
                    size_t o = (size_t)r0 * DD + col;
                    float2 gx = *(const float2*)(g_GA + 2u * NND + o);
                    float2 z  = *(const float2*)(g_Z + o);
                    float2 h  = *(const float2*)(Hm + o);
                    float2 ov;
                    ov.x = z.x * tanhf(gx.x + acc[nt*4+0] + bs0) + (1.f - z.x) * h.x;
                    ov.y = z.y * tanhf(gx.y + acc[nt*4+1] + bs1) + (1.f - z.y) * h.y;
                    *(float2*)(OUT + o) = ov;
                }
                if (r1 < NN) {
                    size_t o = (size_t)r1 * DD + col;
                    float2 gx = *(const float2*)(g_GA + 2u * NND + o);
                    float2 z  = *(const float2*)(g_Z + o);
                    float2 h  = *(const float2*)(Hm + o);
                    float2 ov;
                    ov.x = z.x * tanhf(gx.x + acc[nt*4+2] + bs0) + (1.f - z.x) * h.x;
                    ov.y = z.y * tanhf(gx.y + acc[nt*4+3] + bs1) + (1.f - z.y) * h.y;
                    *(float2*)(OUT + o) = ov;
                }
            }
        }
        if (g + 1 < gates) __syncthreads();
    }
}

// ---------------- elementwise: Z, R, HR tables + next-replay reset ----------

__global__ void k_ew1(const float* __restrict__ Hm, const float* __restrict__ Bb) {
    int i4 = blockIdx.x * blockDim.x + threadIdx.x;
    if (i4 >= NND / 4) return;
    if (i4 < NN) { g_deg[i4] = 0.f; g_cnt[i4] = 0; }   // reset for next replay
    int i = i4 * 4;
    int d = i & (DD - 1);
    float4 ga0 = *(const float4*)(g_GA + i);
    float4 gb0 = *(const float4*)(g_GB + i);
    float4 ga1 = *(const float4*)(g_GA + (size_t)NND + i);
    float4 gb1 = *(const float4*)(g_GB + (size_t)NND + i);
    float4 b0  = *(const float4*)(Bb + d);
    float4 b1  = *(const float4*)(Bb + 64 + d);
    float4 b2  = *(const float4*)(Bb + 128 + d);
    float4 b3  = *(const float4*)(Bb + 192 + d);
    float4 h   = *(const float4*)(Hm + i);
    float4 z, hr;
    z.x = 1.f / (1.f + __expf(-(ga0.x + gb0.x + b0.x + b1.x)));
    z.y = 1.f / (1.f + __expf(-(ga0.y + gb0.y + b0.y + b1.y)));
    z.z = 1.f / (1.f + __expf(-(ga0.z + gb0.z + b0.z + b1.z)));
    z.w = 1.f / (1.f + __expf(-(ga0.w + gb0.w + b0.w + b1.w)));
    hr.x = h.x / (1.f + __expf(-(ga1.x + gb1.x + b2.x + b3.x)));
    hr.y = h.y / (1.f + __expf(-(ga1.y + gb1.y + b2.y + b3.y)));
    hr.z = h.z / (1.f + __expf(-(ga1.z + gb1.z + b2.z + b3.z)));
    hr.w = h.w / (1.f + __expf(-(ga1.w + gb1.w + b2.w + b3.w)));
    *(float4*)(g_Z + i) = z;
    uint32_t h0, l0, h1, l1;
    fsplitpack(make_float2(hr.x, hr.y), h0, l0);
    fsplitpack(make_float2(hr.z, hr.w), h1, l1);
    *(uint2*)(g_HRt + i4 * 2)  = make_uint2(h0, h1);
    *(uint2*)(g_HRlo + i4 * 2) = make_uint2(l0, l1);
}

// ---------------- launch ----------------------------------------------------

extern "C" void kernel_launch(void* const* d_in, const int* in_sizes, int n_in,
                              void* d_out, int out_size) {
    const float* X   = (const float*)d_in[0];
    const void*  EI  = d_in[1];
    const float* EW  = (const float*)d_in[2];
    const float* H   = (const float*)d_in[3];
    const float* LAM = (const float*)d_in[4];
    const float* W   = (const float*)d_in[5];
    const float* B   = (const float*)d_in[6];
    float* OUT = (float*)d_out;

    (void)in_sizes; (void)n_in; (void)out_size;

    cudaFuncSetAttribute(k_gemm_mma, cudaFuncAttributeMaxDynamicSharedMemorySize, DSM_BYTES);

    k_edge_deg<<<(EE / 2 + 255) / 256, 256>>>(EI, EW);               // 0
    k_scan<<<1, 1024>>>();                                           // 1
    k_fillsetup<<<(NH + 255) / 256, 256>>>(EI, EW, X, H, W);         // 2

    dim3 sg((HN + 7) / 8);
    k_spmm1_XH<<<sg, 256>>>(LAM);                                    // 3 (profiled)
    k_spmm2_XH<<<sg, 256>>>(LAM);                                    // 4

    int ntiles = (NN + 63) / 64;
    k_gemm_mma<<<dim3(ntiles, 2), 256, DSM_BYTES>>>(H, B, OUT, 0);   // 5

    k_ew1<<<(NND / 4 + 255) / 256, 256>>>(H, B);                     // 6

    k_spmm1_HR<<<sg, 256>>>(LAM);                                    // 7
    k_spmm2_HR<<<sg, 256>>>(LAM);                                    // 8
    k_gemm_mma<<<dim3(ntiles, 1), 256, DSM_BYTES>>>(H, B, OUT, 2);   // 9
}

// round 12
// speedup vs baseline: 1.0963x; 1.0963x over previous
#include <cuda_runtime.h>
#include <cuda_fp16.h>
#include <cstdint>

#define NN 50000
#define EE 800000
#define DD 64
#define NND (NN * DD)
#define NH (NND / 2)

// ---------------- scratch (device globals; no allocation allowed) ----------
__device__ float g_deg[NN];          // zero-init (BSS); re-zeroed by k_ew1
__device__ int   g_cnt[NN];          // zero-init (BSS); re-zeroed by k_ew1
__device__ int   g_rowptr[NN + 1];
__device__ int   g_cursor[NN];
__device__ int2  g_csrE[EE];         // (src, nrm as int)

// unified fp16 hi/lo tables, word = fp16 pair (2 dims). [row*32+lane]
__device__ uint2 g_XHt[NN * 32],  g_XHlo[NN * 32];   // X,H      (fillsetup)
__device__ uint2 g_T1t[NN * 32],  g_T1lo[NN * 32];   // TX1,TH1  (spmm1)
__device__ uint2 g_T2t[NN * 32],  g_T2lo[NN * 32];   // TX2,TH2  (spmm2)
__device__ uint32_t g_HRt[NN * 32],   g_HRlo[NN * 32];    // ew1
__device__ uint32_t g_THR1t[NN * 32], g_THR1lo[NN * 32];  // spmm1_HR
__device__ uint32_t g_THR2t[NN * 32], g_THR2lo[NN * 32];  // spmm2_HR

__device__ float g_GA[3u * NND];        // Zx, Rx, Hx
__device__ float g_GB[2u * NND];        // Zh, Rh
__device__ float g_Z [NND];

// pre-split weights, transposed to [mat][dout][kin], fp16 hi/lo
__device__ unsigned short g_Wh[18 * 4096];
__device__ unsigned short g_Wl[18 * 4096];

// ---------------- helpers ---------------------------------------------------

__device__ __forceinline__ void fsplit(float x, unsigned short& h, unsigned short& l) {
    __half hh = __float2half_rn(x);
    float r = x - __half2float(hh);
    __half ll = __float2half_rn(r);
    h = *(unsigned short*)&hh;
    l = *(unsigned short*)&ll;
}

__device__ __forceinline__ void fsplitpack(float2 v, uint32_t& hi, uint32_t& lo) {
    unsigned short h0, l0, h1, l1;
    fsplit(v.x, h0, l0); fsplit(v.y, h1, l1);
    hi = (uint32_t)h0 | ((uint32_t)h1 << 16);
    lo = (uint32_t)l0 | ((uint32_t)l1 << 16);
}

__device__ __forceinline__ float2 rec2(uint32_t h, uint32_t l) {
    float2 a = __half22float2(*(__half2*)&h);
    float2 b = __half22float2(*(__half2*)&l);
    return make_float2(a.x + b.x, a.y + b.y);
}

__device__ __forceinline__ int detect_idx64(const unsigned int* ei) {
    unsigned v = ei[2 * (threadIdx.x & 31) + 1];
    unsigned ball = __ballot_sync(0xffffffffu, v == 0u);
    return ball == 0xffffffffu;
}

// ---------------- launch 0: degree + count (2 edges/thread) ----------------

__global__ void k_edge_deg(const void* __restrict__ ei, const float* __restrict__ ew) {
    int idx64 = detect_idx64((const unsigned int*)ei);
    int e2 = blockIdx.x * blockDim.x + threadIdx.x;
    if (e2 >= EE / 2) return;
    int s0, s1, d0, d1;
    if (idx64) {
        const longlong2* ps = (const longlong2*)ei;
        longlong2 sv = ps[e2];
        longlong2 dv = ps[EE / 2 + e2];
        s0 = (int)sv.x; s1 = (int)sv.y;
        d0 = (int)dv.x; d1 = (int)dv.y;
    } else {
        const int2* ps = (const int2*)ei;
        int2 sv = ps[e2];
        int2 dv = ps[EE / 2 + e2];
        s0 = sv.x; s1 = sv.y;
        d0 = dv.x; d1 = dv.y;
    }
    float2 w = ((const float2*)ew)[e2];
    atomicAdd(&g_deg[s0], w.x);
    atomicAdd(&g_deg[s1], w.y);
    atomicAdd(&g_cnt[d0], 1);
    atomicAdd(&g_cnt[d1], 1);
}

// ---------------- launch 1: exclusive scan ---------------------------------

__global__ void k_scan() {
    const int T = 1024;
    int t = threadIdx.x;
    const int CH = (NN + T - 1) / T;
    int beg = t * CH;
    int end = beg + CH; if (end > NN) end = NN; if (beg > NN) beg = NN;
    int s = 0;
    for (int i = beg; i < end; i++) s += g_cnt[i];
    __shared__ int sm[T];
    sm[t] = s; __syncthreads();
    for (int off = 1; off < T; off <<= 1) {
        int v = (t >= off) ? sm[t - off] : 0;
        __syncthreads();
        sm[t] += v;
        __syncthreads();
    }
    int run = sm[t] - s;
    for (int i = beg; i < end; i++) {
        g_rowptr[i] = run; g_cursor[i] = run;
        run += g_cnt[i];
    }
    if (t == 0) g_rowptr[NN] = EE;
}

// ---------------- launch 2: CSR fill + tables + weight split ---------------

__global__ void k_fillsetup(const void* __restrict__ ei, const float* __restrict__ ew,
                            const float* __restrict__ X, const float* __restrict__ Hm,
                            const float* __restrict__ W) {
    int i = blockIdx.x * blockDim.x + threadIdx.x;
    if (i < EE) {
        int idx64 = detect_idx64((const unsigned int*)ei);
        int s, d;
        if (idx64) {
            const long long* p = (const long long*)ei;
            s = (int)p[i]; d = (int)p[EE + i];
        } else {
            const int* p = (const int*)ei;
            s = p[i]; d = p[EE + i];
        }
        float ds = g_deg[s], dd = g_deg[d];
        float is = (ds > 0.f) ? rsqrtf(ds) : 0.f;
        float id = (dd > 0.f) ? rsqrtf(dd) : 0.f;
        float nrm = ew[i] * is * id;
        int pos = atomicAdd(&g_cursor[d], 1);
        g_csrE[pos] = make_int2(s, __float_as_int(nrm));
    }
    if (i < NH) {
        float2 x = ((const float2*)X)[i];
        float2 h = ((const float2*)Hm)[i];
        uint32_t hx, lx, hh, lh;
        fsplitpack(x, hx, lx);
        fsplitpack(h, hh, lh);
        g_XHt[i]  = make_uint2(hx, hh);
        g_XHlo[i] = make_uint2(lx, lh);
    }
    if (i < 18 * 4096) {
        int mat = i >> 12, kin = (i >> 6) & 63, dout = i & 63;
        unsigned short h, l;
        fsplit(W[i], h, l);
        int o = (mat << 12) | (dout << 6) | kin;
        g_Wh[o] = h;
        g_Wl[o] = l;
    }
}

// ---------------- SpMM gathers (low-reg: 4 accs, immediate FMA) -------------

#define ACC2T(t, w, x0, x1, h0, h1) { float2 _v; \
    _v = __half22float2(*(__half2*)&(t).x); x0 += (w) * _v.x; x1 += (w) * _v.y; \
    _v = __half22float2(*(__half2*)&(t).y); h0 += (w) * _v.x; h1 += (w) * _v.y; }

__device__ __forceinline__ void gather2(const uint2* __restrict__ tab, int row, int lane,
    float& rX0, float& rX1, float& rH0, float& rH1)
{
    int beg = g_rowptr[row], end = g_rowptr[row + 1];
    float aX0 = 0.f, aX1 = 0.f, aH0 = 0.f, aH1 = 0.f;
    int e = beg;
    for (; e + 3 < end; e += 4) {
        int2 m0 = g_csrE[e],     m1 = g_csrE[e + 1];
        int2 m2 = g_csrE[e + 2], m3 = g_csrE[e + 3];
        uint2 t0 = tab[m0.x * 32 + lane];
        uint2 t1 = tab[m1.x * 32 + lane];
        uint2 t2 = tab[m2.x * 32 + lane];
        uint2 t3 = tab[m3.x * 32 + lane];
        ACC2T(t0, __int_as_float(m0.y), aX0, aX1, aH0, aH1);
        ACC2T(t1, __int_as_float(m1.y), aX0, aX1, aH0, aH1);
        ACC2T(t2, __int_as_float(m2.y), aX0, aX1, aH0, aH1);
        ACC2T(t3, __int_as_float(m3.y), aX0, aX1, aH0, aH1);
    }
    for (; e < end; e++) {
        int2 m = g_csrE[e];
        uint2 t = tab[m.x * 32 + lane];
        ACC2T(t, __int_as_float(m.y), aX0, aX1, aH0, aH1);
    }
    rX0 = aX0; rX1 = aX1; rH0 = aH0; rH1 = aH1;
}

#define ACC1T(t, w, a0, a1) { float2 _v = __half22float2(*(__half2*)&(t)); \
    a0 += (w) * _v.x; a1 += (w) * _v.y; }

__device__ __forceinline__ void gather1(const uint32_t* __restrict__ tab, int row, int lane,
    float& r0, float& r1)
{
    int beg = g_rowptr[row], end = g_rowptr[row + 1];
    float a0 = 0.f, a1 = 0.f;
    int e = beg;
    for (; e + 3 < end; e += 4) {
        int2 m0 = g_csrE[e],     m1 = g_csrE[e + 1];
        int2 m2 = g_csrE[e + 2], m3 = g_csrE[e + 3];
        uint32_t t0 = tab[m0.x * 32 + lane];
        uint32_t t1 = tab[m1.x * 32 + lane];
        uint32_t t2 = tab[m2.x * 32 + lane];
        uint32_t t3 = tab[m3.x * 32 + lane];
        ACC1T(t0, __int_as_float(m0.y), a0, a1);
        ACC1T(t1, __int_as_float(m1.y), a0, a1);
        ACC1T(t2, __int_as_float(m2.y), a0, a1);
        ACC1T(t3, __int_as_float(m3.y), a0, a1);
    }
    for (; e < end; e++) {
        int2 m = g_csrE[e];
        uint32_t t = tab[m.x * 32 + lane];
        ACC1T(t, __int_as_float(m.y), a0, a1);
    }
    r0 = a0; r1 = a1;
}

// launch 3 (profiled slot): T1 for X and H
__global__ void __launch_bounds__(256, 8) k_spmm1_XH(const float* __restrict__ lam) {
    int warp = threadIdx.x >> 5, lane = threadIdx.x & 31;
    int row = blockIdx.x * 8 + warp;
    if (row >= NN) return;
    float c = 2.f / __ldg(lam);
    float A = c - 1.f, Bc = -c;
    float rX0, rX1, rH0, rH1;
    gather2(g_XHt, row, lane, rX0, rX1, rH0, rH1);
    int b32 = row * 32 + lane;
    uint2 th = g_XHt[b32], tl = g_XHlo[b32];
    float2 vx = rec2(th.x, tl.x);
    float2 vh = rec2(th.y, tl.y);
    float2 oX = make_float2(A * vx.x + Bc * rX0, A * vx.y + Bc * rX1);
    float2 oH = make_float2(A * vh.x + Bc * rH0, A * vh.y + Bc * rH1);
    uint32_t hx, lx, hh, lh;
    fsplitpack(oX, hx, lx);
    fsplitpack(oH, hh, lh);
    g_T1t[b32]  = make_uint2(hx, hh);
    g_T1lo[b32] = make_uint2(lx, lh);
}

// launch 4: T2 for X and H
__global__ void __launch_bounds__(256, 8) k_spmm2_XH(const float* __restrict__ lam) {
    int warp = threadIdx.x >> 5, lane = threadIdx.x & 31;
    int row = blockIdx.x * 8 + warp;
    if (row >= NN) return;
    float c = 2.f / __ldg(lam);
    float A = 2.f * (c - 1.f), Bc = -2.f * c;
    float rX0, rX1, rH0, rH1;
    gather2(g_T1t, row, lane, rX0, rX1, rH0, rH1);
    int b32 = row * 32 + lane;
    uint2 sh = g_T1t[b32], sl = g_T1lo[b32];
    uint2 ah = g_XHt[b32], al = g_XHlo[b32];
    float2 vx = rec2(sh.x, sl.x), vh = rec2(sh.y, sl.y);
    float2 xx = rec2(ah.x, al.x), xh = rec2(ah.y, al.y);
    float2 oX = make_float2(A * vx.x + Bc * rX0 - xx.x, A * vx.y + Bc * rX1 - xx.y);
    float2 oH = make_float2(A * vh.x + Bc * rH0 - xh.x, A * vh.y + Bc * rH1 - xh.y);
    uint32_t hx, lx, hh, lh;
    fsplitpack(oX, hx, lx);
    fsplitpack(oH, hh, lh);
    g_T2t[b32]  = make_uint2(hx, hh);
    g_T2lo[b32] = make_uint2(lx, lh);
}

__global__ void __launch_bounds__(256, 8) k_spmm1_HR(const float* __restrict__ lam) {
    int warp = threadIdx.x >> 5, lane = threadIdx.x & 31;
    int row = blockIdx.x * 8 + warp;
    if (row >= NN) return;
    float c = 2.f / __ldg(lam);
    float A = c - 1.f, Bc = -c;
    float r0, r1;
    gather1(g_HRt, row, lane, r0, r1);
    int b32 = row * 32 + lane;
    float2 v = rec2(g_HRt[b32], g_HRlo[b32]);
    float2 o = make_float2(A * v.x + Bc * r0, A * v.y + Bc * r1);
    uint32_t h, l;
    fsplitpack(o, h, l);
    g_THR1t[b32]  = h;
    g_THR1lo[b32] = l;
}

__global__ void __launch_bounds__(256, 8) k_spmm2_HR(const float* __restrict__ lam) {
    int warp = threadIdx.x >> 5, lane = threadIdx.x & 31;
    int row = blockIdx.x * 8 + warp;
    if (row >= NN) return;
    float c = 2.f / __ldg(lam);
    float A = 2.f * (c - 1.f), Bc = -2.f * c;
    float r0, r1;
    gather1(g_THR1t, row, lane, r0, r1);
    int b32 = row * 32 + lane;
    float2 v = rec2(g_THR1t[b32], g_THR1lo[b32]);
    float2 h = rec2(g_HRt[b32], g_HRlo[b32]);
    float2 o = make_float2(A * v.x + Bc * r0 - h.x, A * v.y + Bc * r1 - h.y);
    uint32_t hh, ll;
    fsplitpack(o, hh, ll);
    g_THR2t[b32]  = hh;
    g_THR2lo[b32] = ll;
}

// ---------------- mma.sync fp16 GEMM (M=64 tile, 2 CTAs/SM) ----------------

__device__ __forceinline__ void mma16816(float* c, uint32_t a0, uint32_t a1,
                                         uint32_t a2, uint32_t a3,
                                         uint32_t b0, uint32_t b1) {
    asm volatile(
        "mma.sync.aligned.m16n8k16.row.col.f32.f16.f16.f32 "
        "{%0,%1,%2,%3}, {%4,%5,%6,%7}, {%8,%9}, {%0,%1,%2,%3};"
        : "+f"(c[0]), "+f"(c[1]), "+f"(c[2]), "+f"(c[3])
        : "r"(a0), "r"(a1), "r"(a2), "r"(a3), "r"(b0), "r"(b1));
}

#define ASTR 200
#define EL_AH 0
#define EL_AL 12800
#define EL_BH 25600
#define EL_BL 38400
#define DSM_BYTES (51200 * 2)

__global__ void __launch_bounds__(256) k_gemm_mma(
    const float* __restrict__ Hm, const float* __restrict__ Bb,
    float* __restrict__ OUT, int whichsel)
{
    extern __shared__ unsigned short sm_el[];
    unsigned short* Ah = sm_el + EL_AH;
    unsigned short* Al = sm_el + EL_AL;
    unsigned short* Bh = sm_el + EL_BH;
    unsigned short* Bl = sm_el + EL_BL;

    int tid = threadIdx.x;
    int wid = tid >> 5, lane = tid & 31;
    int rowbase = blockIdx.x * 64;
    int which = (whichsel == 2) ? 2 : (int)blockIdx.y;

    const uint32_t *hsrc[3], *lsrc[3];
    int st, off;
    float* Cbase; int gates, wstart, wstep;
    if (which == 0) {
        hsrc[0] = (const uint32_t*)g_XHt; lsrc[0] = (const uint32_t*)g_XHlo;
        hsrc[1] = (const uint32_t*)g_T1t; lsrc[1] = (const uint32_t*)g_T1lo;
        hsrc[2] = (const uint32_t*)g_T2t; lsrc[2] = (const uint32_t*)g_T2lo;
        st = 2; off = 0; Cbase = g_GA; gates = 3; wstart = 0; wstep = 2;
    } else if (which == 1) {
        hsrc[0] = (const uint32_t*)g_XHt; lsrc[0] = (const uint32_t*)g_XHlo;
        hsrc[1] = (const uint32_t*)g_T1t; lsrc[1] = (const uint32_t*)g_T1lo;
        hsrc[2] = (const uint32_t*)g_T2t; lsrc[2] = (const uint32_t*)g_T2lo;
        st = 2; off = 1; Cbase = g_GB; gates = 2; wstart = 1; wstep = 2;
    } else {
        hsrc[0] = g_HRt;   lsrc[0] = g_HRlo;
        hsrc[1] = g_THR1t; lsrc[1] = g_THR1lo;
        hsrc[2] = g_THR2t; lsrc[2] = g_THR2lo;
        st = 1; off = 0; Cbase = 0; gates = 1; wstart = 5; wstep = 0;
    }

    uint32_t* Ahw = (uint32_t*)Ah;
    uint32_t* Alw = (uint32_t*)Al;
    #pragma unroll
    for (int c = 0; c < 3; c++) {
        const uint32_t* sh = hsrc[c];
        const uint32_t* sl = lsrc[c];
        #pragma unroll
        for (int i = 0; i < 8; i++) {
            int lin = tid + i * 256;
            int m = lin >> 5;
            int k = lin & 31;
            int grow = rowbase + m;
            uint32_t vh = 0, vl = 0;
            if (grow < NN) {
                int idx = (grow * 32 + k) * st + off;
                vh = sh[idx];
                vl = sl[idx];
            }
            int wo = m * 100 + c * 32 + k;
            Ahw[wo] = vh;
            Alw[wo] = vl;
        }
    }
    __syncthreads();

    int gq = lane >> 2, tg = lane & 3;
    int rw = wid & 3, nh = wid >> 2;
    int mrow = rw * 16;
    const uint32_t* pAh = (const uint32_t*)(Ah + (mrow + gq) * ASTR + tg * 2);
    const uint32_t* pAl = (const uint32_t*)(Al + (mrow + gq) * ASTR + tg * 2);
    const uint32_t* pBh0 = (const uint32_t*)(Bh + gq * ASTR + tg * 2) + nh * 3200;
    const uint32_t* pBl0 = (const uint32_t*)(Bl + gq * ASTR + tg * 2) + nh * 3200;

    for (int g = 0; g < gates; g++) {
        int wsel = wstart + g * wstep;
        #pragma unroll
        for (int c = 0; c < 3; c++) {
            int mat = wsel * 3 + c;
            const uint4* srcH = (const uint4*)(g_Wh + (mat << 12));
            const uint4* srcL = (const uint4*)(g_Wl + (mat << 12));
            #pragma unroll
            for (int i = 0; i < 2; i++) {
                int lin = tid + i * 256;
                int d  = lin >> 3;
                int k8 = (lin & 7) * 8;
                int eo = d * ASTR + c * 64 + k8;
                *(uint4*)(Bh + eo) = srcH[lin];
                *(uint4*)(Bl + eo) = srcL[lin];
            }
        }
        __syncthreads();

        float acc[16];
        #pragma unroll
        for (int i = 0; i < 16; i++) acc[i] = 0.f;

        #pragma unroll 2
        for (int ks = 0; ks < 12; ks++) {
            int kw = ks * 8;
            uint32_t ah0 = pAh[kw], ah1 = pAh[kw + 800];
            uint32_t ah2 = pAh[kw + 4], ah3 = pAh[kw + 804];
            uint32_t al0 = pAl[kw], al1 = pAl[kw + 800];
            uint32_t al2 = pAl[kw + 4], al3 = pAl[kw + 804];
            #pragma unroll
            for (int nt = 0; nt < 4; nt++) {
                int bo = nt * 800 + kw;
                uint32_t bh0 = pBh0[bo], bh1 = pBh0[bo + 4];
                uint32_t bl0 = pBl0[bo], bl1 = pBl0[bo + 4];
                float* a = acc + nt * 4;
                mma16816(a, ah0, ah1, ah2, ah3, bh0, bh1);
                mma16816(a, ah0, ah1, ah2, ah3, bl0, bl1);
                mma16816(a, al0, al1, al2, al3, bh0, bh1);
            }
        }

        int r0 = rowbase + mrow + gq;
        int r1 = r0 + 8;
        if (whichsel != 2) {
            float* C = Cbase + (size_t)g * NND;
            #pragma unroll
            for (int nt = 0; nt < 4; nt++) {
                int col = (nh * 4 + nt) * 8 + tg * 2;
                if (r0 < NN) *(float2*)(C + (size_t)r0 * DD + col) = make_float2(acc[nt*4+0], acc[nt*4+1]);
                if (r1 < NN) *(float2*)(C + (size_t)r1 * DD + col) = make_float2(acc[nt*4+2], acc[nt*4+3]);
            }
        } else {
            #pragma unroll
            for (int nt = 0; nt < 4; nt++) {
                int col = (nh * 4 + nt) * 8 + tg * 2;
                float bs0 = __ldg(Bb + 256 + col)     + __ldg(Bb + 320 + col);
                float bs1 = __ldg(Bb + 256 + col + 1) + __ldg(Bb + 320 + col + 1);
                if (r0 < NN) {
                    size_t o = (size_t)r0 * DD + col;
                    float2 gx = *(const float2*)(g_GA + 2u * NND + o);
                    float2 z  = *(const float2*)(g_Z + o);
                    float2 h  = *(const float2*)(Hm + o);
                    float2 ov;
                    ov.x = z.x * tanhf(gx.x + acc[nt*4+0] + bs0) + (1.f - z.x) * h.x;
                    ov.y = z.y * tanhf(gx.y + acc[nt*4+1] + bs1) + (1.f - z.y) * h.y;
                    *(float2*)(OUT + o) = ov;
                }
                if (r1 < NN) {
                    size_t o = (size_t)r1 * DD + col;
                    float2 gx = *(const float2*)(g_GA + 2u * NND + o);
                    float2 z  = *(const float2*)(g_Z + o);
                    float2 h  = *(const float2*)(Hm + o);
                    float2 ov;
                    ov.x = z.x * tanhf(gx.x + acc[nt*4+2] + bs0) + (1.f - z.x) * h.x;
                    ov.y = z.y * tanhf(gx.y + acc[nt*4+3] + bs1) + (1.f - z.y) * h.y;
                    *(float2*)(OUT + o) = ov;
                }
            }
        }
        if (g + 1 < gates) __syncthreads();
    }
}

// ---------------- elementwise: Z, R, HR tables + next-replay reset ----------

__global__ void k_ew1(const float* __restrict__ Hm, const float* __restrict__ Bb) {
    int i4 = blockIdx.x * blockDim.x + threadIdx.x;
    if (i4 >= NND / 4) return;
    if (i4 < NN) { g_deg[i4] = 0.f; g_cnt[i4] = 0; }   // reset for next replay
    int i = i4 * 4;
    int d = i & (DD - 1);
    float4 ga0 = *(const float4*)(g_GA + i);
    float4 gb0 = *(const float4*)(g_GB + i);
    float4 ga1 = *(const float4*)(g_GA + (size_t)NND + i);
    float4 gb1 = *(const float4*)(g_GB + (size_t)NND + i);
    float4 b0  = *(const float4*)(Bb + d);
    float4 b1  = *(const float4*)(Bb + 64 + d);
    float4 b2  = *(const float4*)(Bb + 128 + d);
    float4 b3  = *(const float4*)(Bb + 192 + d);
    float4 h   = *(const float4*)(Hm + i);
    float4 z, hr;
    z.x = 1.f / (1.f + __expf(-(ga0.x + gb0.x + b0.x + b1.x)));
    z.y = 1.f / (1.f + __expf(-(ga0.y + gb0.y + b0.y + b1.y)));
    z.z = 1.f / (1.f + __expf(-(ga0.z + gb0.z + b0.z + b1.z)));
    z.w = 1.f / (1.f + __expf(-(ga0.w + gb0.w + b0.w + b1.w)));
    hr.x = h.x / (1.f + __expf(-(ga1.x + gb1.x + b2.x + b3.x)));
    hr.y = h.y / (1.f + __expf(-(ga1.y + gb1.y + b2.y + b3.y)));
    hr.z = h.z / (1.f + __expf(-(ga1.z + gb1.z + b2.z + b3.z)));
    hr.w = h.w / (1.f + __expf(-(ga1.w + gb1.w + b2.w + b3.w)));
    *(float4*)(g_Z + i) = z;
    uint32_t h0, l0, h1, l1;
    fsplitpack(make_float2(hr.x, hr.y), h0, l0);
    fsplitpack(make_float2(hr.z, hr.w), h1, l1);
    *(uint2*)(g_HRt + i4 * 2)  = make_uint2(h0, h1);
    *(uint2*)(g_HRlo + i4 * 2) = make_uint2(l0, l1);
}

// ---------------- launch ----------------------------------------------------

extern "C" void kernel_launch(void* const* d_in, const int* in_sizes, int n_in,
                              void* d_out, int out_size) {
    const float* X   = (const float*)d_in[0];
    const void*  EI  = d_in[1];
    const float* EW  = (const float*)d_in[2];
    const float* H   = (const float*)d_in[3];
    const float* LAM = (const float*)d_in[4];
    const float* W   = (const float*)d_in[5];
    const float* B   = (const float*)d_in[6];
    float* OUT = (float*)d_out;

    (void)in_sizes; (void)n_in; (void)out_size;

    cudaFuncSetAttribute(k_gemm_mma, cudaFuncAttributeMaxDynamicSharedMemorySize, DSM_BYTES);

    k_edge_deg<<<(EE / 2 + 255) / 256, 256>>>(EI, EW);               // 0
    k_scan<<<1, 1024>>>();                                           // 1
    k_fillsetup<<<(NH + 255) / 256, 256>>>(EI, EW, X, H, W);         // 2

    dim3 sg((NN + 7) / 8);
    k_spmm1_XH<<<sg, 256>>>(LAM);                                    // 3 (profiled)
    k_spmm2_XH<<<sg, 256>>>(LAM);                                    // 4

    int ntiles = (NN + 63) / 64;
    k_gemm_mma<<<dim3(ntiles, 2), 256, DSM_BYTES>>>(H, B, OUT, 0);   // 5

    k_ew1<<<(NND / 4 + 255) / 256, 256>>>(H, B);                     // 6

    k_spmm1_HR<<<sg, 256>>>(LAM);                                    // 7
    k_spmm2_HR<<<sg, 256>>>(LAM);                                    // 8
    k_gemm_mma<<<dim3(ntiles, 1), 256, DSM_BYTES>>>(H, B, OUT, 2);   // 9
}

// round 13
// speedup vs baseline: 1.0967x; 1.0004x over previous
#include <cuda_runtime.h>
#include <cuda_bf16.h>
#include <cstdint>

#define NN 50000
#define EE 800000
#define DD 64
#define NND (NN * DD)
#define NH (NND / 2)

// ---------------- scratch (device globals; no allocation allowed) ----------
__device__ float g_deg[NN];          // zero-init (BSS); re-zeroed by k_ew1
__device__ int   g_cnt[NN];          // zero-init (BSS); re-zeroed by k_ew1
__device__ int   g_rowptr[NN + 1];
__device__ int   g_cursor[NN];
__device__ int2  g_csrE[EE];         // (src, nrm as int)

// unified bf16 hi/lo tables, word = bf16 pair (2 dims). [row*32+lane]
__device__ uint2 g_XHt[NN * 32],  g_XHlo[NN * 32];   // X,H      (fillsetup)
__device__ uint2 g_T1t[NN * 32],  g_T1lo[NN * 32];   // TX1,TH1  (spmm1)
__device__ uint2 g_T2t[NN * 32],  g_T2lo[NN * 32];   // TX2,TH2  (spmm2)
__device__ uint32_t g_HRt[NN * 32],   g_HRlo[NN * 32];    // ew1
__device__ uint32_t g_THR1t[NN * 32], g_THR1lo[NN * 32];  // spmm1_HR
__device__ uint32_t g_THR2t[NN * 32], g_THR2lo[NN * 32];  // spmm2_HR

__device__ float g_GA[3u * NND];        // Zx, Rx, Hx
__device__ float g_GB[2u * NND];        // Zh, Rh
__device__ float g_Z [NND];

// pre-split weights, transposed to [mat][dout][kin], bf16 hi/lo
__device__ unsigned short g_Wh[18 * 4096];
__device__ unsigned short g_Wl[18 * 4096];

// ---------------- helpers ---------------------------------------------------

__device__ __forceinline__ void fsplit(float x, unsigned short& h, unsigned short& l) {
    __nv_bfloat16 bh = __float2bfloat16_rn(x);
    float r = x - __bfloat162float(bh);
    __nv_bfloat16 bl = __float2bfloat16_rn(r);
    h = *(unsigned short*)&bh;
    l = *(unsigned short*)&bl;
}

__device__ __forceinline__ void fsplitpack(float2 v, uint32_t& hi, uint32_t& lo) {
    unsigned short h0, l0, h1, l1;
    fsplit(v.x, h0, l0); fsplit(v.y, h1, l1);
    hi = (uint32_t)h0 | ((uint32_t)h1 << 16);
    lo = (uint32_t)l0 | ((uint32_t)l1 << 16);
}

// bf16 pair word -> two floats (pure ALU bit ops, no cvt pipe)
__device__ __forceinline__ float bflo(uint32_t w) { return __uint_as_float(w << 16); }
__device__ __forceinline__ float bfhi(uint32_t w) { return __uint_as_float(w & 0xffff0000u); }

__device__ __forceinline__ float2 rec2(uint32_t h, uint32_t l) {
    return make_float2(bflo(h) + bflo(l), bfhi(h) + bfhi(l));
}

__device__ __forceinline__ int detect_idx64(const unsigned int* ei) {
    unsigned v = ei[2 * (threadIdx.x & 31) + 1];
    unsigned ball = __ballot_sync(0xffffffffu, v == 0u);
    return ball == 0xffffffffu;
}

// ---------------- launch 0: degree + count (2 edges/thread) ----------------

__global__ void k_edge_deg(const void* __restrict__ ei, const float* __restrict__ ew) {
    int idx64 = detect_idx64((const unsigned int*)ei);
    int e2 = blockIdx.x * blockDim.x + threadIdx.x;
    if (e2 >= EE / 2) return;
    int s0, s1, d0, d1;
    if (idx64) {
        const longlong2* ps = (const longlong2*)ei;
        longlong2 sv = ps[e2];
        longlong2 dv = ps[EE / 2 + e2];
        s0 = (int)sv.x; s1 = (int)sv.y;
        d0 = (int)dv.x; d1 = (int)dv.y;
    } else {
        const int2* ps = (const int2*)ei;
        int2 sv = ps[e2];
        int2 dv = ps[EE / 2 + e2];
        s0 = sv.x; s1 = sv.y;
        d0 = dv.x; d1 = dv.y;
    }
    float2 w = ((const float2*)ew)[e2];
    atomicAdd(&g_deg[s0], w.x);
    atomicAdd(&g_deg[s1], w.y);
    atomicAdd(&g_cnt[d0], 1);
    atomicAdd(&g_cnt[d1], 1);
}

// ---------------- launch 1: exclusive scan ---------------------------------

__global__ void k_scan() {
    const int T = 1024;
    int t = threadIdx.x;
    const int CH = (NN + T - 1) / T;
    int beg = t * CH;
    int end = beg + CH; if (end > NN) end = NN; if (beg > NN) beg = NN;
    int s = 0;
    for (int i = beg; i < end; i++) s += g_cnt[i];
    __shared__ int sm[T];
    sm[t] = s; __syncthreads();
    for (int off = 1; off < T; off <<= 1) {
        int v = (t >= off) ? sm[t - off] : 0;
        __syncthreads();
        sm[t] += v;
        __syncthreads();
    }
    int run = sm[t] - s;
    for (int i = beg; i < end; i++) {
        g_rowptr[i] = run; g_cursor[i] = run;
        run += g_cnt[i];
    }
    if (t == 0) g_rowptr[NN] = EE;
}

// ---------------- launch 2: CSR fill + tables + weight split ---------------

__global__ void k_fillsetup(const void* __restrict__ ei, const float* __restrict__ ew,
                            const float* __restrict__ X, const float* __restrict__ Hm,
                            const float* __restrict__ W) {
    int i = blockIdx.x * blockDim.x + threadIdx.x;
    if (i < EE) {
        int idx64 = detect_idx64((const unsigned int*)ei);
        int s, d;
        if (idx64) {
            const long long* p = (const long long*)ei;
            s = (int)p[i]; d = (int)p[EE + i];
        } else {
            const int* p = (const int*)ei;
            s = p[i]; d = p[EE + i];
        }
        float ds = g_deg[s], dd = g_deg[d];
        float is = (ds > 0.f) ? rsqrtf(ds) : 0.f;
        float id = (dd > 0.f) ? rsqrtf(dd) : 0.f;
        float nrm = ew[i] * is * id;
        int pos = atomicAdd(&g_cursor[d], 1);
        g_csrE[pos] = make_int2(s, __float_as_int(nrm));
    }
    if (i < NH) {
        float2 x = ((const float2*)X)[i];
        float2 h = ((const float2*)Hm)[i];
        uint32_t hx, lx, hh, lh;
        fsplitpack(x, hx, lx);
        fsplitpack(h, hh, lh);
        g_XHt[i]  = make_uint2(hx, hh);
        g_XHlo[i] = make_uint2(lx, lh);
    }
    if (i < 18 * 4096) {
        int mat = i >> 12, kin = (i >> 6) & 63, dout = i & 63;
        unsigned short h, l;
        fsplit(W[i], h, l);
        int o = (mat << 12) | (dout << 6) | kin;
        g_Wh[o] = h;
        g_Wl[o] = l;
    }
}

// ---------------- SpMM gathers (low-reg, bf16 ALU decode) -------------------

#define ACC2T(t, w, x0, x1, h0, h1) { \
    x0 += (w) * bflo((t).x); x1 += (w) * bfhi((t).x); \
    h0 += (w) * bflo((t).y); h1 += (w) * bfhi((t).y); }

__device__ __forceinline__ void gather2(const uint2* __restrict__ tab, int row, int lane,
    float& rX0, float& rX1, float& rH0, float& rH1)
{
    int beg = g_rowptr[row], end = g_rowptr[row + 1];
    float aX0 = 0.f, aX1 = 0.f, aH0 = 0.f, aH1 = 0.f;
    int e = beg;
    for (; e + 3 < end; e += 4) {
        int2 m0 = g_csrE[e],     m1 = g_csrE[e + 1];
        int2 m2 = g_csrE[e + 2], m3 = g_csrE[e + 3];
        uint2 t0 = tab[m0.x * 32 + lane];
        uint2 t1 = tab[m1.x * 32 + lane];
        uint2 t2 = tab[m2.x * 32 + lane];
        uint2 t3 = tab[m3.x * 32 + lane];
        ACC2T(t0, __int_as_float(m0.y), aX0, aX1, aH0, aH1);
        ACC2T(t1, __int_as_float(m1.y), aX0, aX1, aH0, aH1);
        ACC2T(t2, __int_as_float(m2.y), aX0, aX1, aH0, aH1);
        ACC2T(t3, __int_as_float(m3.y), aX0, aX1, aH0, aH1);
    }
    for (; e < end; e++) {
        int2 m = g_csrE[e];
        uint2 t = tab[m.x * 32 + lane];
        ACC2T(t, __int_as_float(m.y), aX0, aX1, aH0, aH1);
    }
    rX0 = aX0; rX1 = aX1; rH0 = aH0; rH1 = aH1;
}

#define ACC1T(t, w, a0, a1) { \
    a0 += (w) * bflo(t); a1 += (w) * bfhi(t); }

__device__ __forceinline__ void gather1(const uint32_t* __restrict__ tab, int row, int lane,
    float& r0, float& r1)
{
    int beg = g_rowptr[row], end = g_rowptr[row + 1];
    float a0 = 0.f, a1 = 0.f;
    int e = beg;
    for (; e + 3 < end; e += 4) {
        int2 m0 = g_csrE[e],     m1 = g_csrE[e + 1];
        int2 m2 = g_csrE[e + 2], m3 = g_csrE[e + 3];
        uint32_t t0 = tab[m0.x * 32 + lane];
        uint32_t t1 = tab[m1.x * 32 + lane];
        uint32_t t2 = tab[m2.x * 32 + lane];
        uint32_t t3 = tab[m3.x * 32 + lane];
        ACC1T(t0, __int_as_float(m0.y), a0, a1);
        ACC1T(t1, __int_as_float(m1.y), a0, a1);
        ACC1T(t2, __int_as_float(m2.y), a0, a1);
        ACC1T(t3, __int_as_float(m3.y), a0, a1);
    }
    for (; e < end; e++) {
        int2 m = g_csrE[e];
        uint32_t t = tab[m.x * 32 + lane];
        ACC1T(t, __int_as_float(m.y), a0, a1);
    }
    r0 = a0; r1 = a1;
}

// launch 3 (profiled slot): T1 for X and H
__global__ void __launch_bounds__(256, 8) k_spmm1_XH(const float* __restrict__ lam) {
    int warp = threadIdx.x >> 5, lane = threadIdx.x & 31;
    int row = blockIdx.x * 8 + warp;
    if (row >= NN) return;
    float c = 2.f / __ldg(lam);
    float A = c - 1.f, Bc = -c;
    float rX0, rX1, rH0, rH1;
    gather2(g_XHt, row, lane, rX0, rX1, rH0, rH1);
    int b32 = row * 32 + lane;
    uint2 th = g_XHt[b32], tl = g_XHlo[b32];
    float2 vx = rec2(th.x, tl.x);
    float2 vh = rec2(th.y, tl.y);
    float2 oX = make_float2(A * vx.x + Bc * rX0, A * vx.y + Bc * rX1);
    float2 oH = make_float2(A * vh.x + Bc * rH0, A * vh.y + Bc * rH1);
    uint32_t hx, lx, hh, lh;
    fsplitpack(oX, hx, lx);
    fsplitpack(oH, hh, lh);
    g_T1t[b32]  = make_uint2(hx, hh);
    g_T1lo[b32] = make_uint2(lx, lh);
}

// launch 4: T2 for X and H
__global__ void __launch_bounds__(256, 8) k_spmm2_XH(const float* __restrict__ lam) {
    int warp = threadIdx.x >> 5, lane = threadIdx.x & 31;
    int row = blockIdx.x * 8 + warp;
    if (row >= NN) return;
    float c = 2.f / __ldg(lam);
    float A = 2.f * (c - 1.f), Bc = -2.f * c;
    float rX0, rX1, rH0, rH1;
    gather2(g_T1t, row, lane, rX0, rX1, rH0, rH1);
    int b32 = row * 32 + lane;
    uint2 sh = g_T1t[b32], sl = g_T1lo[b32];
    uint2 ah = g_XHt[b32], al = g_XHlo[b32];
    float2 vx = rec2(sh.x, sl.x), vh = rec2(sh.y, sl.y);
    float2 xx = rec2(ah.x, al.x), xh = rec2(ah.y, al.y);
    float2 oX = make_float2(A * vx.x + Bc * rX0 - xx.x, A * vx.y + Bc * rX1 - xx.y);
    float2 oH = make_float2(A * vh.x + Bc * rH0 - xh.x, A * vh.y + Bc * rH1 - xh.y);
    uint32_t hx, lx, hh, lh;
    fsplitpack(oX, hx, lx);
    fsplitpack(oH, hh, lh);
    g_T2t[b32]  = make_uint2(hx, hh);
    g_T2lo[b32] = make_uint2(lx, lh);
}

__global__ void __launch_bounds__(256, 8) k_spmm1_HR(const float* __restrict__ lam) {
    int warp = threadIdx.x >> 5, lane = threadIdx.x & 31;
    int row = blockIdx.x * 8 + warp;
    if (row >= NN) return;
    float c = 2.f / __ldg(lam);
    float A = c - 1.f, Bc = -c;
    float r0, r1;
    gather1(g_HRt, row, lane, r0, r1);
    int b32 = row * 32 + lane;
    float2 v = rec2(g_HRt[b32], g_HRlo[b32]);
    float2 o = make_float2(A * v.x + Bc * r0, A * v.y + Bc * r1);
    uint32_t h, l;
    fsplitpack(o, h, l);
    g_THR1t[b32]  = h;
    g_THR1lo[b32] = l;
}

__global__ void __launch_bounds__(256, 8) k_spmm2_HR(const float* __restrict__ lam) {
    int warp = threadIdx.x >> 5, lane = threadIdx.x & 31;
    int row = blockIdx.x * 8 + warp;
    if (row >= NN) return;
    float c = 2.f / __ldg(lam);
    float A = 2.f * (c - 1.f), Bc = -2.f * c;
    float r0, r1;
    gather1(g_THR1t, row, lane, r0, r1);
    int b32 = row * 32 + lane;
    float2 v = rec2(g_THR1t[b32], g_THR1lo[b32]);
    float2 h = rec2(g_HRt[b32], g_HRlo[b32]);
    float2 o = make_float2(A * v.x + Bc * r0 - h.x, A * v.y + Bc * r1 - h.y);
    uint32_t hh, ll;
    fsplitpack(o, hh, ll);
    g_THR2t[b32]  = hh;
    g_THR2lo[b32] = ll;
}

// ---------------- mma.sync bf16 GEMM (M=64 tile, 2 CTAs/SM) ----------------

__device__ __forceinline__ void mma16816(float* c, uint32_t a0, uint32_t a1,
                                         uint32_t a2, uint32_t a3,
                                         uint32_t b0, uint32_t b1) {
    asm volatile(
        "mma.sync.aligned.m16n8k16.row.col.f32.bf16.bf16.f32 "
        "{%0,%1,%2,%3}, {%4,%5,%6,%7}, {%8,%9}, {%0,%1,%2,%3};"
        : "+f"(c[0]), "+f"(c[1]), "+f"(c[2]), "+f"(c[3])
        : "r"(a0), "r"(a1), "r"(a2), "r"(a3), "r"(b0), "r"(b1));
}

#define ASTR 200
#define EL_AH 0
#define EL_AL 12800
#define EL_BH 25600
#define EL_BL 38400
#define DSM_BYTES (51200 * 2)

__global__ void __launch_bounds__(256) k_gemm_mma(
    const float* __restrict__ Hm, const float* __restrict__ Bb,
    float* __restrict__ OUT, int whichsel)
{
    extern __shared__ unsigned short sm_el[];
    unsigned short* Ah = sm_el + EL_AH;
    unsigned short* Al = sm_el + EL_AL;
    unsigned short* Bh = sm_el + EL_BH;
    unsigned short* Bl = sm_el + EL_BL;

    int tid = threadIdx.x;
    int wid = tid >> 5, lane = tid & 31;
    int rowbase = blockIdx.x * 64;
    int which = (whichsel == 2) ? 2 : (int)blockIdx.y;

    const uint32_t *hsrc[3], *lsrc[3];
    int st, off;
    float* Cbase; int gates, wstart, wstep;
    if (which == 0) {
        hsrc[0] = (const uint32_t*)g_XHt; lsrc[0] = (const uint32_t*)g_XHlo;
        hsrc[1] = (const uint32_t*)g_T1t; lsrc[1] = (const uint32_t*)g_T1lo;
        hsrc[2] = (const uint32_t*)g_T2t; lsrc[2] = (const uint32_t*)g_T2lo;
        st = 2; off = 0; Cbase = g_GA; gates = 3; wstart = 0; wstep = 2;
    } else if (which == 1) {
        hsrc[0] = (const uint32_t*)g_XHt; lsrc[0] = (const uint32_t*)g_XHlo;
        hsrc[1] = (const uint32_t*)g_T1t; lsrc[1] = (const uint32_t*)g_T1lo;
        hsrc[2] = (const uint32_t*)g_T2t; lsrc[2] = (const uint32_t*)g_T2lo;
        st = 2; off = 1; Cbase = g_GB; gates = 2; wstart = 1; wstep = 2;
    } else {
        hsrc[0] = g_HRt;   lsrc[0] = g_HRlo;
        hsrc[1] = g_THR1t; lsrc[1] = g_THR1lo;
        hsrc[2] = g_THR2t; lsrc[2] = g_THR2lo;
        st = 1; off = 0; Cbase = 0; gates = 1; wstart = 5; wstep = 0;
    }

    uint32_t* Ahw = (uint32_t*)Ah;
    uint32_t* Alw = (uint32_t*)Al;
    #pragma unroll
    for (int c = 0; c < 3; c++) {
        const uint32_t* sh = hsrc[c];
        const uint32_t* sl = lsrc[c];
        #pragma unroll
        for (int i = 0; i < 8; i++) {
            int lin = tid + i * 256;
            int m = lin >> 5;
            int k = lin & 31;
            int grow = rowbase + m;
            uint32_t vh = 0, vl = 0;
            if (grow < NN) {
                int idx = (grow * 32 + k) * st + off;
                vh = sh[idx];
                vl = sl[idx];
            }
            int wo = m * 100 + c * 32 + k;
            Ahw[wo] = vh;
            Alw[wo] = vl;
        }
    }
    __syncthreads();

    int gq = lane >> 2, tg = lane & 3;
    int rw = wid & 3, nh = wid >> 2;
    int mrow = rw * 16;
    const uint32_t* pAh = (const uint32_t*)(Ah + (mrow + gq) * ASTR + tg * 2);
    const uint32_t* pAl = (const uint32_t*)(Al + (mrow + gq) * ASTR + tg * 2);
    const uint32_t* pBh0 = (const uint32_t*)(Bh + gq * ASTR + tg * 2) + nh * 3200;
    const uint32_t* pBl0 = (const uint32_t*)(Bl + gq * ASTR + tg * 2) + nh * 3200;

    for (int g = 0; g < gates; g++) {
        int wsel = wstart + g * wstep;
        #pragma unroll
        for (int c = 0; c < 3; c++) {
            int mat = wsel * 3 + c;
            const uint4* srcH = (const uint4*)(g_Wh + (mat << 12));
            const uint4* srcL = (const uint4*)(g_Wl + (mat << 12));
            #pragma unroll
            for (int i = 0; i < 2; i++) {
                int lin = tid + i * 256;
                int d  = lin >> 3;
                int k8 = (lin & 7) * 8;
                int eo = d * ASTR + c * 64 + k8;
                *(uint4*)(Bh + eo) = srcH[lin];
                *(uint4*)(Bl + eo) = srcL[lin];
            }
        }
        __syncthreads();

        float acc[16];
        #pragma unroll
        for (int i = 0; i < 16; i++) acc[i] = 0.f;

        #pragma unroll 2
        for (int ks = 0; ks < 12; ks++) {
            int kw = ks * 8;
            uint32_t ah0 = pAh[kw], ah1 = pAh[kw + 800];
            uint32_t ah2 = pAh[kw + 4], ah3 = pAh[kw + 804];
            uint32_t al0 = pAl[kw], al1 = pAl[kw + 800];
            uint32_t al2 = pAl[kw + 4], al3 = pAl[kw + 804];
            #pragma unroll
            for (int nt = 0; nt < 4; nt++) {
                int bo = nt * 800 + kw;
                uint32_t bh0 = pBh0[bo], bh1 = pBh0[bo + 4];
                uint32_t bl0 = pBl0[bo], bl1 = pBl0[bo + 4];
                float* a = acc + nt * 4;
                mma16816(a, ah0, ah1, ah2, ah3, bh0, bh1);
                mma16816(a, ah0, ah1, ah2, ah3, bl0, bl1);
                mma16816(a, al0, al1, al2, al3, bh0, bh1);
            }
        }

        int r0 = rowbase + mrow + gq;
        int r1 = r0 + 8;
        if (whichsel != 2) {
            float* C = Cbase + (size_t)g * NND;
            #pragma unroll
            for (int nt = 0; nt < 4; nt++) {
                int col = (nh * 4 + nt) * 8 + tg * 2;
                if (r0 < NN) *(float2*)(C + (size_t)r0 * DD + col) = make_float2(acc[nt*4+0], acc[nt*4+1]);
                if (r1 < NN) *(float2*)(C + (size_t)r1 * DD + col) = make_float2(acc[nt*4+2], acc[nt*4+3]);
            }
        } else {
            #pragma unroll
            for (int nt = 0; nt < 4; nt++) {
                int col = (nh * 4 + nt) * 8 + tg * 2;
                float bs0 = __ldg(Bb + 256 + col)     + __ldg(Bb + 320 + col);
                float bs1 = __ldg(Bb + 256 + col + 1) + __ldg(Bb + 320 + col + 1);
                if (r0 < NN) {
                    size_t o = (size_t)r0 * DD + col;
                    float2 gx = *(const float2*)(g_GA + 2u * NND + o);
                    float2 z  = *(const float2*)(g_Z + o);
                    float2 h  = *(const float2*)(Hm + o);
                    float2 ov;
                    ov.x = z.x * tanhf(gx.x + acc[nt*4+0] + bs0) + (1.f - z.x) * h.x;
                    ov.y = z.y * tanhf(gx.y + acc[nt*4+1] + bs1) + (1.f - z.y) * h.y;
                    *(float2*)(OUT + o) = ov;
                }
                if (r1 < NN) {
                    size_t o = (size_t)r1 * DD + col;
                    float2 gx = *(const float2*)(g_GA + 2u * NND + o);
                    float2 z  = *(const float2*)(g_Z + o);
                    float2 h  = *(const float2*)(Hm + o);
                    float2 ov;
                    ov.x = z.x * tanhf(gx.x + acc[nt*4+2] + bs0) + (1.f - z.x) * h.x;
                    ov.y = z.y * tanhf(gx.y + acc[nt*4+3] + bs1) + (1.f - z.y) * h.y;
                    *(float2*)(OUT + o) = ov;
                }
            }
        }
        if (g + 1 < gates) __syncthreads();
    }
}

// ---------------- elementwise: Z, R, HR tables + next-replay reset ----------

__global__ void k_ew1(const float* __restrict__ Hm, const float* __restrict__ Bb) {
    int i4 = blockIdx.x * blockDim.x + threadIdx.x;
    if (i4 >= NND / 4) return;
    if (i4 < NN) { g_deg[i4] = 0.f; g_cnt[i4] = 0; }   // reset for next replay
    int i = i4 * 4;
    int d = i & (DD - 1);
    float4 ga0 = *(const float4*)(g_GA + i);
    float4 gb0 = *(const float4*)(g_GB + i);
    float4 ga1 = *(const float4*)(g_GA + (size_t)NND + i);
    float4 gb1 = *(const float4*)(g_GB + (size_t)NND + i);
    float4 b0  = *(const float4*)(Bb + d);
    float4 b1  = *(const float4*)(Bb + 64 + d);
    float4 b2  = *(const float4*)(Bb + 128 + d);
    float4 b3  = *(const float4*)(Bb + 192 + d);
    float4 h   = *(const float4*)(Hm + i);
    float4 z, hr;
    z.x = 1.f / (1.f + __expf(-(ga0.x + gb0.x + b0.x + b1.x)));
    z.y = 1.f / (1.f + __expf(-(ga0.y + gb0.y + b0.y + b1.y)));
    z.z = 1.f / (1.f + __expf(-(ga0.z + gb0.z + b0.z + b1.z)));
    z.w = 1.f / (1.f + __expf(-(ga0.w + gb0.w + b0.w + b1.w)));
    hr.x = h.x / (1.f + __expf(-(ga1.x + gb1.x + b2.x + b3.x)));
    hr.y = h.y / (1.f + __expf(-(ga1.y + gb1.y + b2.y + b3.y)));
    hr.z = h.z / (1.f + __expf(-(ga1.z + gb1.z + b2.z + b3.z)));
    hr.w = h.w / (1.f + __expf(-(ga1.w + gb1.w + b2.w + b3.w)));
    *(float4*)(g_Z + i) = z;
    uint32_t h0, l0, h1, l1;
    fsplitpack(make_float2(hr.x, hr.y), h0, l0);
    fsplitpack(make_float2(hr.z, hr.w), h1, l1);
    *(uint2*)(g_HRt + i4 * 2)  = make_uint2(h0, h1);
    *(uint2*)(g_HRlo + i4 * 2) = make_uint2(l0, l1);
}

// ---------------- launch ----------------------------------------------------

extern "C" void kernel_launch(void* const* d_in, const int* in_sizes, int n_in,
                              void* d_out, int out_size) {
    const float* X   = (const float*)d_in[0];
    const void*  EI  = d_in[1];
    const float* EW  = (const float*)d_in[2];
    const float* H   = (const float*)d_in[3];
    const float* LAM = (const float*)d_in[4];
    const float* W   = (const float*)d_in[5];
    const float* B   = (const float*)d_in[6];
    float* OUT = (float*)d_out;

    (void)in_sizes; (void)n_in; (void)out_size;

    cudaFuncSetAttribute(k_gemm_mma, cudaFuncAttributeMaxDynamicSharedMemorySize, DSM_BYTES);

    k_edge_deg<<<(EE / 2 + 255) / 256, 256>>>(EI, EW);               // 0
    k_scan<<<1, 1024>>>();                                           // 1
    k_fillsetup<<<(NH + 255) / 256, 256>>>(EI, EW, X, H, W);         // 2

    dim3 sg((NN + 7) / 8);
    k_spmm1_XH<<<sg, 256>>>(LAM);                                    // 3 (profiled)
    k_spmm2_XH<<<sg, 256>>>(LAM);                                    // 4

    int ntiles = (NN + 63) / 64;
    k_gemm_mma<<<dim3(ntiles, 2), 256, DSM_BYTES>>>(H, B, OUT, 0);   // 5

    k_ew1<<<(NND / 4 + 255) / 256, 256>>>(H, B);                     // 6

    k_spmm1_HR<<<sg, 256>>>(LAM);                                    // 7
    k_spmm2_HR<<<sg, 256>>>(LAM);                                    // 8
    k_gemm_mma<<<dim3(ntiles, 1), 256, DSM_BYTES>>>(H, B, OUT, 2);   // 9
}